// round 2
// baseline (speedup 1.0000x reference)
#include <cuda_runtime.h>
#include <math.h>

#define S    2048
#define DM   1024
#define NH   16
#define DK   64
#define DFF  4096

// ---------------- scratch (device globals — no allocation allowed) ----------
__device__ float g_norm1[S * DM];
__device__ float g_h    [S * DM];
__device__ float g_q    [S * DM];
__device__ float g_k    [S * DM];
__device__ float g_v    [S * DM];
__device__ float g_ctx  [S * DM];
__device__ float g_mha  [S * DM];
__device__ float g_part1[S * DM];
__device__ float g_norm2[S * DM];
__device__ float g_ff1  [S * DFF];

// ---------------- warp/block reduction helpers ------------------------------
__device__ __forceinline__ float warp_sum(float v) {
#pragma unroll
    for (int o = 16; o > 0; o >>= 1) v += __shfl_xor_sync(0xffffffffu, v, o);
    return v;
}
__device__ __forceinline__ float warp_max(float v) {
#pragma unroll
    for (int o = 16; o > 0; o >>= 1) v = fmaxf(v, __shfl_xor_sync(0xffffffffu, v, o));
    return v;
}
// block-wide (256 threads) reductions via one smem round
__device__ __forceinline__ float block_sum(float v, float* red) {
    const int tid = threadIdx.x;
    v = warp_sum(v);
    if ((tid & 31) == 0) red[tid >> 5] = v;
    __syncthreads();
    float r = (tid < 8) ? red[tid] : 0.f;
    r = warp_sum(r);                     // warp 0 lanes 0..7 carry partials
    if (tid == 0) red[0] = r;
    __syncthreads();
    return red[0];
}
__device__ __forceinline__ float block_max(float v, float* red) {
    const int tid = threadIdx.x;
    v = warp_max(v);
    if ((tid & 31) == 0) red[tid >> 5] = v;
    __syncthreads();
    float r = (tid < 8) ? red[tid] : -3.0e38f;
    r = warp_max(r);
    if (tid == 0) red[0] = r;
    __syncthreads();
    return red[0];
}

// ---------------- LayerNorm: y = g*((x-mean)/(std+eps)) + b -----------------
__global__ void __launch_bounds__(256) ln_kernel(const float* __restrict__ x,
                                                 const float* __restrict__ g,
                                                 const float* __restrict__ b,
                                                 float* __restrict__ y)
{
    const int row = blockIdx.x;
    const float4* xr = (const float4*)(x + (size_t)row * DM);
    float4* yr = (float4*)(y + (size_t)row * DM);
    __shared__ float red[8];
    const int tid = threadIdx.x;

    float4 xv = xr[tid];                       // DM/4 = 256 = blockDim
    float s = xv.x + xv.y + xv.z + xv.w;
    const float mean = block_sum(s, red) * (1.f / DM);
    __syncthreads();

    float dx = xv.x - mean, dy = xv.y - mean, dz = xv.z - mean, dw = xv.w - mean;
    float v = dx * dx + dy * dy + dz * dz + dw * dw;
    const float var = block_sum(v, red) * (1.f / DM);
    const float inv = 1.f / (sqrtf(var) + 1e-6f);

    float4 gv = ((const float4*)g)[tid];
    float4 bv = ((const float4*)b)[tid];
    float4 o;
    o.x = gv.x * (dx * inv) + bv.x;
    o.y = gv.y * (dy * inv) + bv.y;
    o.z = gv.z * (dz * inv) + bv.z;
    o.w = gv.w * (dw * inv) + bv.w;
    yr[tid] = o;
}

// ---------------- SGEMM: C = A[MxK] @ B[KxN] + bias (+res) (+relu) ----------
// 128x128 tile, BK=8, 256 threads, 8x8 microtile, double-buffered smem.
// Requires M%128==0, N%128==0, K%16==0 (true at every call site).
template<int RELU, int RES>
__global__ void __launch_bounds__(256) sgemm_kernel(
    const float* __restrict__ A, const float* __restrict__ B,
    const float* __restrict__ bias, const float* __restrict__ Dres,
    float* __restrict__ C, int M, int N, int K)
{
    __shared__ float As[2][8][128];
    __shared__ float Bs[2][8][128];
    const int tid = threadIdx.x;
    const int bm = blockIdx.y * 128;
    const int bn = blockIdx.x * 128;

    const int aRow = tid >> 1;             // 0..127
    const int aCol = (tid & 1) << 2;       // 0 or 4
    const int bRow = tid >> 5;             // 0..7
    const int bCol = (tid & 31) << 2;      // 0..124

    const int tm = (tid >> 4) << 3;
    const int tn = (tid & 15) << 3;

    float acc[8][8];
#pragma unroll
    for (int i = 0; i < 8; i++)
#pragma unroll
        for (int j = 0; j < 8; j++) acc[i][j] = 0.f;

    const float* Ap = A + (size_t)(bm + aRow) * K + aCol;
    const float* Bp = B + (size_t)bRow * N + bn + bCol;

    // prologue: stage 0
    {
        float4 a4 = *(const float4*)(Ap);
        As[0][aCol + 0][aRow] = a4.x;
        As[0][aCol + 1][aRow] = a4.y;
        As[0][aCol + 2][aRow] = a4.z;
        As[0][aCol + 3][aRow] = a4.w;
        *(float4*)&Bs[0][bRow][bCol] = *(const float4*)(Bp);
    }
    __syncthreads();

    int buf = 0;
    for (int k0 = 0; k0 < K; k0 += 8) {
        // prefetch next tile into registers (no sync needed yet)
        float4 a4n, b4n;
        const int k1 = k0 + 8;
        if (k1 < K) {
            a4n = *(const float4*)(Ap + k1);
            b4n = *(const float4*)(Bp + (size_t)k1 * N);
        }

#pragma unroll
        for (int kk = 0; kk < 8; kk++) {
            float ra[8], rb[8];
#pragma unroll
            for (int i = 0; i < 8; i++) ra[i] = As[buf][kk][tm + i];
#pragma unroll
            for (int j = 0; j < 8; j++) rb[j] = Bs[buf][kk][tn + j];
#pragma unroll
            for (int i = 0; i < 8; i++)
#pragma unroll
                for (int j = 0; j < 8; j++)
                    acc[i][j] = fmaf(ra[i], rb[j], acc[i][j]);
        }

        if (k1 < K) {
            const int nb = buf ^ 1;
            As[nb][aCol + 0][aRow] = a4n.x;
            As[nb][aCol + 1][aRow] = a4n.y;
            As[nb][aCol + 2][aRow] = a4n.z;
            As[nb][aCol + 3][aRow] = a4n.w;
            *(float4*)&Bs[nb][bRow][bCol] = b4n;
            __syncthreads();
            buf = nb;
        }
    }

    // epilogue: vectorized float4 stores (tn is 8-aligned)
#pragma unroll
    for (int i = 0; i < 8; i++) {
        const size_t row = (size_t)(bm + tm + i);
        float4* Crow = (float4*)(C + row * N + bn + tn);
        const float4* biasv = (const float4*)(bias + bn + tn);
        float4 c0, c1;
        c0.x = acc[i][0]; c0.y = acc[i][1]; c0.z = acc[i][2]; c0.w = acc[i][3];
        c1.x = acc[i][4]; c1.y = acc[i][5]; c1.z = acc[i][6]; c1.w = acc[i][7];
        float4 b0 = biasv[0], b1 = biasv[1];
        c0.x += b0.x; c0.y += b0.y; c0.z += b0.z; c0.w += b0.w;
        c1.x += b1.x; c1.y += b1.y; c1.z += b1.z; c1.w += b1.w;
        if (RES) {
            const float4* Dv = (const float4*)(Dres + row * N + bn + tn);
            float4 d0 = Dv[0], d1 = Dv[1];
            c0.x += d0.x; c0.y += d0.y; c0.z += d0.z; c0.w += d0.w;
            c1.x += d1.x; c1.y += d1.y; c1.z += d1.z; c1.w += d1.w;
        }
        if (RELU) {
            c0.x = fmaxf(c0.x, 0.f); c0.y = fmaxf(c0.y, 0.f);
            c0.z = fmaxf(c0.z, 0.f); c0.w = fmaxf(c0.w, 0.f);
            c1.x = fmaxf(c1.x, 0.f); c1.y = fmaxf(c1.y, 0.f);
            c1.z = fmaxf(c1.z, 0.f); c1.w = fmaxf(c1.w, 0.f);
        }
        Crow[0] = c0; Crow[1] = c1;
    }
}

// ---------------- attention scores: P[h,q,k] = Q_h . K_h / 8 (causal tiles) -
__global__ void __launch_bounds__(256) scores_kernel(
    const float* __restrict__ Q, const float* __restrict__ Kc,
    float* __restrict__ P)
{
    const int kt = blockIdx.x, qt = blockIdx.y, h = blockIdx.z;
    if (kt > qt) return;   // fully-masked tile; softmax writes the zeros

    __shared__ float Qs[64][65];  // [c][r] transposed
    __shared__ float Ks[64][65];
    const int tid = threadIdx.x;

    for (int idx = tid; idx < 64 * 64; idx += 256) {
        const int r = idx >> 6, c = idx & 63;
        Qs[c][r] = Q [(size_t)(qt * 64 + r) * DM + h * DK + c];
        Ks[c][r] = Kc[(size_t)(kt * 64 + r) * DM + h * DK + c];
    }
    __syncthreads();

    const int tm = (tid >> 4) << 2;
    const int tn = (tid & 15) << 2;
    float acc[4][4] = {};
#pragma unroll 8
    for (int c = 0; c < 64; c++) {
        float ra[4], rb[4];
#pragma unroll
        for (int i = 0; i < 4; i++) ra[i] = Qs[c][tm + i];
#pragma unroll
        for (int j = 0; j < 4; j++) rb[j] = Ks[c][tn + j];
#pragma unroll
        for (int i = 0; i < 4; i++)
#pragma unroll
            for (int j = 0; j < 4; j++)
                acc[i][j] = fmaf(ra[i], rb[j], acc[i][j]);
    }

    float* Pb = P + (size_t)h * S * S;
#pragma unroll
    for (int i = 0; i < 4; i++) {
        float4 v0;
        v0.x = acc[i][0] * 0.125f; v0.y = acc[i][1] * 0.125f;
        v0.z = acc[i][2] * 0.125f; v0.w = acc[i][3] * 0.125f;
        *(float4*)&Pb[(size_t)(qt * 64 + tm + i) * S + kt * 64 + tn] = v0;
    }
}

// ---------------- in-place causal softmax over rows of P --------------------
__global__ void __launch_bounds__(256) softmax_kernel(float* __restrict__ P)
{
    const int row = blockIdx.x;          // h*S + q
    const int qi = row & (S - 1);
    float* p = P + (size_t)row * S;
    const int n = qi + 1;
    __shared__ float red[8];
    const int tid = threadIdx.x;

    float m = -3.0e38f;
    for (int j = tid; j < n; j += 256) m = fmaxf(m, p[j]);
    m = block_max(m, red);
    __syncthreads();

    float sum = 0.f;
    for (int j = tid; j < n; j += 256) { float e = expf(p[j] - m); p[j] = e; sum += e; }
    sum = block_sum(sum, red);
    const float inv = 1.f / sum;

    for (int j = tid; j < n; j += 256) p[j] *= inv;
    for (int j = n + tid; j < S; j += 256) p[j] = 0.f;  // masked cols must be 0
}

// ---------------- ctx[q, h*64+c] = sum_k P[h,q,k] * V[k, h*64+c] (causal) ---
__global__ void __launch_bounds__(256) ctx_kernel(
    const float* __restrict__ P, const float* __restrict__ V,
    float* __restrict__ Cx)
{
    const int qt = blockIdx.x, h = blockIdx.y;
    __shared__ float Ps[64][65];
    __shared__ float Vs[64][65];
    const int tid = threadIdx.x;
    const int tm = (tid >> 4) << 2;
    const int tn = (tid & 15) << 2;
    float acc[4][4] = {};
    const float* Ph = P + (size_t)h * S * S;

    for (int kb = 0; kb <= qt; kb++) {
        for (int idx = tid; idx < 64 * 64; idx += 256) {
            const int r = idx >> 6, c = idx & 63;
            Ps[r][c] = Ph[(size_t)(qt * 64 + r) * S + kb * 64 + c];
            Vs[r][c] = V [(size_t)(kb * 64 + r) * DM + h * DK + c];
        }
        __syncthreads();
#pragma unroll 8
        for (int kk = 0; kk < 64; kk++) {
            float ra[4], rb[4];
#pragma unroll
            for (int i = 0; i < 4; i++) ra[i] = Ps[tm + i][kk];
#pragma unroll
            for (int j = 0; j < 4; j++) rb[j] = Vs[kk][tn + j];
#pragma unroll
            for (int i = 0; i < 4; i++)
#pragma unroll
                for (int j = 0; j < 4; j++)
                    acc[i][j] = fmaf(ra[i], rb[j], acc[i][j]);
        }
        __syncthreads();
    }

#pragma unroll
    for (int i = 0; i < 4; i++) {
        float4 v0;
        v0.x = acc[i][0]; v0.y = acc[i][1]; v0.z = acc[i][2]; v0.w = acc[i][3];
        *(float4*)&Cx[(size_t)(qt * 64 + tm + i) * DM + h * DK + tn] = v0;
    }
}

// ---------------- host orchestration ----------------------------------------
extern "C" void kernel_launch(void* const* d_in, const int* in_sizes, int n_in,
                              void* d_out, int out_size)
{
    const float* x     = (const float*)d_in[0];
    const float* g1    = (const float*)d_in[1];
    const float* beta1 = (const float*)d_in[2];
    const float* W_in  = (const float*)d_in[3];
    const float* b_in  = (const float*)d_in[4];
    const float* Wq    = (const float*)d_in[5];
    const float* bq    = (const float*)d_in[6];
    const float* Wk    = (const float*)d_in[7];
    const float* bk    = (const float*)d_in[8];
    const float* Wv    = (const float*)d_in[9];
    const float* bv    = (const float*)d_in[10];
    const float* Wo    = (const float*)d_in[11];
    const float* bo    = (const float*)d_in[12];
    const float* W2    = (const float*)d_in[13];
    const float* b2    = (const float*)d_in[14];
    const float* g2    = (const float*)d_in[15];
    const float* beta2 = (const float*)d_in[16];
    const float* Wf1   = (const float*)d_in[17];
    const float* bf1   = (const float*)d_in[18];
    const float* Wf2   = (const float*)d_in[19];
    const float* bf2   = (const float*)d_in[20];

    float* out  = (float*)d_out;                       // [S, DM]
    float* attn = (float*)d_out + (size_t)S * DM;      // [NH, S, S]

    float *p_norm1, *p_h, *p_q, *p_k, *p_v, *p_ctx, *p_mha, *p_part1, *p_norm2, *p_ff1;
    cudaGetSymbolAddress((void**)&p_norm1, g_norm1);
    cudaGetSymbolAddress((void**)&p_h,     g_h);
    cudaGetSymbolAddress((void**)&p_q,     g_q);
    cudaGetSymbolAddress((void**)&p_k,     g_k);
    cudaGetSymbolAddress((void**)&p_v,     g_v);
    cudaGetSymbolAddress((void**)&p_ctx,   g_ctx);
    cudaGetSymbolAddress((void**)&p_mha,   g_mha);
    cudaGetSymbolAddress((void**)&p_part1, g_part1);
    cudaGetSymbolAddress((void**)&p_norm2, g_norm2);
    cudaGetSymbolAddress((void**)&p_ff1,   g_ff1);

    // 1. LN1
    ln_kernel<<<S, 256>>>(x, g1, beta1, p_norm1);

    // 2. h = norm1 @ W_in + b_in
    sgemm_kernel<0,0><<<dim3(DM/128, S/128), 256>>>(p_norm1, W_in, b_in, nullptr, p_h, S, DM, DM);

    // 3. q/k/v
    sgemm_kernel<0,0><<<dim3(DM/128, S/128), 256>>>(p_h, Wq, bq, nullptr, p_q, S, DM, DM);
    sgemm_kernel<0,0><<<dim3(DM/128, S/128), 256>>>(p_h, Wk, bk, nullptr, p_k, S, DM, DM);
    sgemm_kernel<0,0><<<dim3(DM/128, S/128), 256>>>(p_h, Wv, bv, nullptr, p_v, S, DM, DM);

    // 4. scores (into attn output region), 5. softmax in place
    scores_kernel<<<dim3(S/64, S/64, NH), 256>>>(p_q, p_k, attn);
    softmax_kernel<<<NH * S, 256>>>(attn);

    // 6. ctx = attn @ v
    ctx_kernel<<<dim3(S/64, NH), 256>>>(attn, p_v, p_ctx);

    // 7. mha = ctx @ Wo + bo
    sgemm_kernel<0,0><<<dim3(DM/128, S/128), 256>>>(p_ctx, Wo, bo, nullptr, p_mha, S, DM, DM);

    // 8. part1 = x + mha @ W2 + b2
    sgemm_kernel<0,1><<<dim3(DM/128, S/128), 256>>>(p_mha, W2, b2, x, p_part1, S, DM, DM);

    // 9. LN2
    ln_kernel<<<S, 256>>>(p_part1, g2, beta2, p_norm2);

    // 10. ff1 = relu(norm2 @ Wf1 + bf1)
    sgemm_kernel<1,0><<<dim3(DFF/128, S/128), 256>>>(p_norm2, Wf1, bf1, nullptr, p_ff1, S, DFF, DM);

    // 11. out = norm2 + ff1 @ Wf2 + bf2
    sgemm_kernel<0,1><<<dim3(DM/128, S/128), 256>>>(p_ff1, Wf2, bf2, p_norm2, out, S, DM, DFF);
}

// round 3
// speedup vs baseline: 1.0465x; 1.0465x over previous
#include <cuda_runtime.h>
#include <math.h>

#define S    2048
#define DM   1024
#define NH   16
#define DK   64
#define DFF  4096

// ---------------- scratch (device globals — no allocation allowed) ----------
__device__ float g_norm1[S * DM];
__device__ float g_h    [S * DM];
__device__ float g_q    [S * DM];
__device__ float g_k    [S * DM];
__device__ float g_v    [S * DM];
__device__ float g_ctx  [S * DM];
__device__ float g_mha  [S * DM];
__device__ float g_part1[S * DM];
__device__ float g_norm2[S * DM];
__device__ float g_ff1  [S * DFF];

// ---------------- warp/block reduction helpers ------------------------------
__device__ __forceinline__ float warp_sum(float v) {
#pragma unroll
    for (int o = 16; o > 0; o >>= 1) v += __shfl_xor_sync(0xffffffffu, v, o);
    return v;
}
__device__ __forceinline__ float warp_max(float v) {
#pragma unroll
    for (int o = 16; o > 0; o >>= 1) v = fmaxf(v, __shfl_xor_sync(0xffffffffu, v, o));
    return v;
}
__device__ __forceinline__ float block_sum(float v, float* red) {
    const int tid = threadIdx.x;
    v = warp_sum(v);
    if ((tid & 31) == 0) red[tid >> 5] = v;
    __syncthreads();
    float r = (tid < 8) ? red[tid] : 0.f;
    r = warp_sum(r);
    if (tid == 0) red[0] = r;
    __syncthreads();
    return red[0];
}
__device__ __forceinline__ float block_max(float v, float* red) {
    const int tid = threadIdx.x;
    v = warp_max(v);
    if ((tid & 31) == 0) red[tid >> 5] = v;
    __syncthreads();
    float r = (tid < 8) ? red[tid] : -3.0e38f;
    r = warp_max(r);
    if (tid == 0) red[0] = r;
    __syncthreads();
    return red[0];
}

// ---------------- LayerNorm --------------------------------------------------
__global__ void __launch_bounds__(256) ln_kernel(const float* __restrict__ x,
                                                 const float* __restrict__ g,
                                                 const float* __restrict__ b,
                                                 float* __restrict__ y)
{
    const int row = blockIdx.x;
    const float4* xr = (const float4*)(x + (size_t)row * DM);
    float4* yr = (float4*)(y + (size_t)row * DM);
    __shared__ float red[8];
    const int tid = threadIdx.x;

    float4 xv = xr[tid];
    float s = xv.x + xv.y + xv.z + xv.w;
    const float mean = block_sum(s, red) * (1.f / DM);
    __syncthreads();

    float dx = xv.x - mean, dy = xv.y - mean, dz = xv.z - mean, dw = xv.w - mean;
    float v = dx * dx + dy * dy + dz * dz + dw * dw;
    const float var = block_sum(v, red) * (1.f / DM);
    const float inv = 1.f / (sqrtf(var) + 1e-6f);

    float4 gv = ((const float4*)g)[tid];
    float4 bv = ((const float4*)b)[tid];
    float4 o;
    o.x = gv.x * (dx * inv) + bv.x;
    o.y = gv.y * (dy * inv) + bv.y;
    o.z = gv.z * (dz * inv) + bv.z;
    o.w = gv.w * (dw * inv) + bv.w;
    yr[tid] = o;
}

// ---------------- SGEMM core: 128x128 tile, BK=8, 256 thr, 8x8 micro --------
// smem double-buffered across k-tiles; register double-buffered fragments.
template<int RELU, int RES>
__device__ __forceinline__ void sgemm_body(
    const float* __restrict__ A, const float* __restrict__ B,
    const float* __restrict__ bias, const float* __restrict__ Dres,
    float* __restrict__ C, int N, int K,
    float (*As)[8][128], float (*Bs)[8][128])
{
    const int tid = threadIdx.x;
    const int bm = blockIdx.y * 128;
    const int bn = blockIdx.x * 128;

    const int aRow = tid >> 1;
    const int aCol = (tid & 1) << 2;
    const int bRow = tid >> 5;
    const int bCol = (tid & 31) << 2;

    const int tm = (tid >> 4) << 3;
    const int tn = (tid & 15) << 3;

    float acc[8][8];
#pragma unroll
    for (int i = 0; i < 8; i++)
#pragma unroll
        for (int j = 0; j < 8; j++) acc[i][j] = 0.f;

    const float* Ap = A + (size_t)(bm + aRow) * K + aCol;
    const float* Bp = B + (size_t)bRow * N + bn + bCol;

    {   // prologue: stage 0
        float4 a4 = *(const float4*)(Ap);
        As[0][aCol + 0][aRow] = a4.x;
        As[0][aCol + 1][aRow] = a4.y;
        As[0][aCol + 2][aRow] = a4.z;
        As[0][aCol + 3][aRow] = a4.w;
        *(float4*)&Bs[0][bRow][bCol] = *(const float4*)(Bp);
    }
    __syncthreads();

    int buf = 0;
    for (int k0 = 0; k0 < K; k0 += 8) {
        const int k1 = k0 + 8;
        float4 a4n, b4n;
        if (k1 < K) {           // global prefetch (long-latency, issued first)
            a4n = *(const float4*)(Ap + k1);
            b4n = *(const float4*)(Bp + (size_t)k1 * N);
        }

        float ra[2][8], rb[2][8];
#pragma unroll
        for (int i = 0; i < 8; i++) { ra[0][i] = As[buf][0][tm + i]; rb[0][i] = Bs[buf][0][tn + i]; }

#pragma unroll
        for (int kk = 0; kk < 8; kk++) {
            const int cur = kk & 1, nxt = cur ^ 1;
            if (kk < 7) {
#pragma unroll
                for (int i = 0; i < 8; i++) { ra[nxt][i] = As[buf][kk + 1][tm + i]; rb[nxt][i] = Bs[buf][kk + 1][tn + i]; }
            }
#pragma unroll
            for (int i = 0; i < 8; i++)
#pragma unroll
                for (int j = 0; j < 8; j++)
                    acc[i][j] = fmaf(ra[cur][i], rb[cur][j], acc[i][j]);
        }

        if (k1 < K) {
            const int nb = buf ^ 1;
            As[nb][aCol + 0][aRow] = a4n.x;
            As[nb][aCol + 1][aRow] = a4n.y;
            As[nb][aCol + 2][aRow] = a4n.z;
            As[nb][aCol + 3][aRow] = a4n.w;
            *(float4*)&Bs[nb][bRow][bCol] = b4n;
            __syncthreads();
            buf = nb;
        }
    }

#pragma unroll
    for (int i = 0; i < 8; i++) {
        const size_t row = (size_t)(bm + tm + i);
        float4* Crow = (float4*)(C + row * N + bn + tn);
        const float4* biasv = (const float4*)(bias + bn + tn);
        float4 c0, c1;
        c0.x = acc[i][0]; c0.y = acc[i][1]; c0.z = acc[i][2]; c0.w = acc[i][3];
        c1.x = acc[i][4]; c1.y = acc[i][5]; c1.z = acc[i][6]; c1.w = acc[i][7];
        float4 b0 = biasv[0], b1 = biasv[1];
        c0.x += b0.x; c0.y += b0.y; c0.z += b0.z; c0.w += b0.w;
        c1.x += b1.x; c1.y += b1.y; c1.z += b1.z; c1.w += b1.w;
        if (RES) {
            const float4* Dv = (const float4*)(Dres + row * N + bn + tn);
            float4 d0 = Dv[0], d1 = Dv[1];
            c0.x += d0.x; c0.y += d0.y; c0.z += d0.z; c0.w += d0.w;
            c1.x += d1.x; c1.y += d1.y; c1.z += d1.z; c1.w += d1.w;
        }
        if (RELU) {
            c0.x = fmaxf(c0.x, 0.f); c0.y = fmaxf(c0.y, 0.f);
            c0.z = fmaxf(c0.z, 0.f); c0.w = fmaxf(c0.w, 0.f);
            c1.x = fmaxf(c1.x, 0.f); c1.y = fmaxf(c1.y, 0.f);
            c1.z = fmaxf(c1.z, 0.f); c1.w = fmaxf(c1.w, 0.f);
        }
        Crow[0] = c0; Crow[1] = c1;
    }
}

template<int RELU, int RES>
__global__ void __launch_bounds__(256) sgemm_kernel(
    const float* __restrict__ A, const float* __restrict__ B,
    const float* __restrict__ bias, const float* __restrict__ Dres,
    float* __restrict__ C, int N, int K)
{
    __shared__ float As[2][8][128];
    __shared__ float Bs[2][8][128];
    sgemm_body<RELU, RES>(A, B, bias, Dres, C, N, K, As, Bs);
}

// batched QKV: blockIdx.z selects which projection
__global__ void __launch_bounds__(256) qkv_kernel(
    const float* __restrict__ Hm,
    const float* __restrict__ Wq, const float* __restrict__ bq, float* __restrict__ Oq,
    const float* __restrict__ Wk, const float* __restrict__ bk, float* __restrict__ Ok,
    const float* __restrict__ Wv, const float* __restrict__ bv, float* __restrict__ Ov)
{
    __shared__ float As[2][8][128];
    __shared__ float Bs[2][8][128];
    const float* W; const float* b; float* O;
    if (blockIdx.z == 0)      { W = Wq; b = bq; O = Oq; }
    else if (blockIdx.z == 1) { W = Wk; b = bk; O = Ok; }
    else                      { W = Wv; b = bv; O = Ov; }
    sgemm_body<0, 0>(Hm, W, b, nullptr, O, DM, DM, As, Bs);
}

// ---------------- scores: 128x128 tiles, K=64, 8x8 micro (causal) -----------
__global__ void __launch_bounds__(256) scores_kernel(
    const float* __restrict__ Q, const float* __restrict__ Kc,
    float* __restrict__ P)
{
    const int kt = blockIdx.x, qt = blockIdx.y, h = blockIdx.z;
    if (kt > qt) return;     // fully-masked tile; softmax writes the zeros

    __shared__ float Qs[64][132];   // [k][row]
    __shared__ float Ks[64][132];   // [k][col]
    const int tid = threadIdx.x;

    for (int idx = tid; idx < 128 * 16; idx += 256) {
        const int r = idx >> 4, c4 = (idx & 15) << 2;
        float4 qv = *(const float4*)&Q [(size_t)(qt * 128 + r) * DM + h * DK + c4];
        Qs[c4 + 0][r] = qv.x; Qs[c4 + 1][r] = qv.y; Qs[c4 + 2][r] = qv.z; Qs[c4 + 3][r] = qv.w;
        float4 kv = *(const float4*)&Kc[(size_t)(kt * 128 + r) * DM + h * DK + c4];
        Ks[c4 + 0][r] = kv.x; Ks[c4 + 1][r] = kv.y; Ks[c4 + 2][r] = kv.z; Ks[c4 + 3][r] = kv.w;
    }
    __syncthreads();

    const int tm = (tid >> 4) << 3;
    const int tn = (tid & 15) << 3;
    float acc[8][8];
#pragma unroll
    for (int i = 0; i < 8; i++)
#pragma unroll
        for (int j = 0; j < 8; j++) acc[i][j] = 0.f;

    float ra[2][8], rb[2][8];
#pragma unroll
    for (int i = 0; i < 8; i++) { ra[0][i] = Qs[0][tm + i]; rb[0][i] = Ks[0][tn + i]; }
#pragma unroll
    for (int kk = 0; kk < 64; kk++) {
        const int cur = kk & 1, nxt = cur ^ 1;
        if (kk < 63) {
#pragma unroll
            for (int i = 0; i < 8; i++) { ra[nxt][i] = Qs[kk + 1][tm + i]; rb[nxt][i] = Ks[kk + 1][tn + i]; }
        }
#pragma unroll
        for (int i = 0; i < 8; i++)
#pragma unroll
            for (int j = 0; j < 8; j++)
                acc[i][j] = fmaf(ra[cur][i], rb[cur][j], acc[i][j]);
    }

    float* Pb = P + (size_t)h * S * S;
#pragma unroll
    for (int i = 0; i < 8; i++) {
        float4 v0, v1;
        v0.x = acc[i][0] * 0.125f; v0.y = acc[i][1] * 0.125f;
        v0.z = acc[i][2] * 0.125f; v0.w = acc[i][3] * 0.125f;
        v1.x = acc[i][4] * 0.125f; v1.y = acc[i][5] * 0.125f;
        v1.z = acc[i][6] * 0.125f; v1.w = acc[i][7] * 0.125f;
        float* dst = &Pb[(size_t)(qt * 128 + tm + i) * S + kt * 128 + tn];
        *(float4*)dst = v0;
        *(float4*)(dst + 4) = v1;
    }
}

// ---------------- in-place causal softmax over rows of P --------------------
__global__ void __launch_bounds__(256) softmax_kernel(float* __restrict__ P)
{
    const int row = blockIdx.x;          // h*S + q
    const int qi = row & (S - 1);
    float* p = P + (size_t)row * S;
    const int n = qi + 1;
    __shared__ float red[8];
    const int tid = threadIdx.x;

    float m = -3.0e38f;
    for (int j = tid; j < n; j += 256) m = fmaxf(m, p[j]);
    m = block_max(m, red);
    __syncthreads();

    float sum = 0.f;
    for (int j = tid; j < n; j += 256) { float e = expf(p[j] - m); p[j] = e; sum += e; }
    sum = block_sum(sum, red);
    const float inv = 1.f / sum;

    for (int j = tid; j < n; j += 256) p[j] *= inv;
    for (int j = n + tid; j < S; j += 256) p[j] = 0.f;
}

// ---------------- ctx: 128x64 tiles, 128 thr, 8x8 micro (causal) ------------
__global__ void __launch_bounds__(128) ctx_kernel(
    const float* __restrict__ P, const float* __restrict__ V,
    float* __restrict__ Cx)
{
    const int qt = blockIdx.x, h = blockIdx.y;
    __shared__ float Ps[128][132];  // [k][q] (transposed)
    __shared__ float Vs[128][68];   // [k][c]
    const int tid = threadIdx.x;
    const int tm = (tid >> 3) << 3;     // 0..120
    const int tn = (tid & 7) << 3;      // 0..56
    float acc[8][8];
#pragma unroll
    for (int i = 0; i < 8; i++)
#pragma unroll
        for (int j = 0; j < 8; j++) acc[i][j] = 0.f;

    const float* Ph = P + (size_t)h * S * S;

    for (int kb = 0; kb <= qt; kb++) {
        // P tile [128q x 128k] -> transposed smem
        for (int idx = tid; idx < 128 * 32; idx += 128) {
            const int r = idx >> 5, c4 = (idx & 31) << 2;
            float4 pv = *(const float4*)&Ph[(size_t)(qt * 128 + r) * S + kb * 128 + c4];
            Ps[c4 + 0][r] = pv.x; Ps[c4 + 1][r] = pv.y; Ps[c4 + 2][r] = pv.z; Ps[c4 + 3][r] = pv.w;
        }
        // V tile [128k x 64c] direct
        for (int idx = tid; idx < 128 * 16; idx += 128) {
            const int r = idx >> 4, c4 = (idx & 15) << 2;
            *(float4*)&Vs[r][c4] = *(const float4*)&V[(size_t)(kb * 128 + r) * DM + h * DK + c4];
        }
        __syncthreads();

        float ra[2][8], rb[2][8];
#pragma unroll
        for (int i = 0; i < 8; i++) { ra[0][i] = Ps[0][tm + i]; rb[0][i] = Vs[0][tn + i]; }
#pragma unroll 16
        for (int kk = 0; kk < 128; kk++) {
            const int cur = kk & 1, nxt = cur ^ 1;
            if (kk < 127) {
#pragma unroll
                for (int i = 0; i < 8; i++) { ra[nxt][i] = Ps[kk + 1][tm + i]; rb[nxt][i] = Vs[kk + 1][tn + i]; }
            }
#pragma unroll
            for (int i = 0; i < 8; i++)
#pragma unroll
                for (int j = 0; j < 8; j++)
                    acc[i][j] = fmaf(ra[cur][i], rb[cur][j], acc[i][j]);
        }
        __syncthreads();
    }

#pragma unroll
    for (int i = 0; i < 8; i++) {
        float* dst = &Cx[(size_t)(qt * 128 + tm + i) * DM + h * DK + tn];
        float4 v0, v1;
        v0.x = acc[i][0]; v0.y = acc[i][1]; v0.z = acc[i][2]; v0.w = acc[i][3];
        v1.x = acc[i][4]; v1.y = acc[i][5]; v1.z = acc[i][6]; v1.w = acc[i][7];
        *(float4*)dst = v0;
        *(float4*)(dst + 4) = v1;
    }
}

// ---------------- host orchestration ----------------------------------------
extern "C" void kernel_launch(void* const* d_in, const int* in_sizes, int n_in,
                              void* d_out, int out_size)
{
    const float* x     = (const float*)d_in[0];
    const float* g1    = (const float*)d_in[1];
    const float* beta1 = (const float*)d_in[2];
    const float* W_in  = (const float*)d_in[3];
    const float* b_in  = (const float*)d_in[4];
    const float* Wq    = (const float*)d_in[5];
    const float* bq    = (const float*)d_in[6];
    const float* Wk    = (const float*)d_in[7];
    const float* bk    = (const float*)d_in[8];
    const float* Wv    = (const float*)d_in[9];
    const float* bv    = (const float*)d_in[10];
    const float* Wo    = (const float*)d_in[11];
    const float* bo    = (const float*)d_in[12];
    const float* W2    = (const float*)d_in[13];
    const float* b2    = (const float*)d_in[14];
    const float* g2    = (const float*)d_in[15];
    const float* beta2 = (const float*)d_in[16];
    const float* Wf1   = (const float*)d_in[17];
    const float* bf1   = (const float*)d_in[18];
    const float* Wf2   = (const float*)d_in[19];
    const float* bf2   = (const float*)d_in[20];

    float* out  = (float*)d_out;                       // [S, DM]
    float* attn = (float*)d_out + (size_t)S * DM;      // [NH, S, S]

    float *p_norm1, *p_h, *p_q, *p_k, *p_v, *p_ctx, *p_mha, *p_part1, *p_norm2, *p_ff1;
    cudaGetSymbolAddress((void**)&p_norm1, g_norm1);
    cudaGetSymbolAddress((void**)&p_h,     g_h);
    cudaGetSymbolAddress((void**)&p_q,     g_q);
    cudaGetSymbolAddress((void**)&p_k,     g_k);
    cudaGetSymbolAddress((void**)&p_v,     g_v);
    cudaGetSymbolAddress((void**)&p_ctx,   g_ctx);
    cudaGetSymbolAddress((void**)&p_mha,   g_mha);
    cudaGetSymbolAddress((void**)&p_part1, g_part1);
    cudaGetSymbolAddress((void**)&p_norm2, g_norm2);
    cudaGetSymbolAddress((void**)&p_ff1,   g_ff1);

    // 1. LN1
    ln_kernel<<<S, 256>>>(x, g1, beta1, p_norm1);

    // 2. h = norm1 @ W_in + b_in
    sgemm_kernel<0,0><<<dim3(DM/128, S/128), 256>>>(p_norm1, W_in, b_in, nullptr, p_h, DM, DM);

    // 3. q/k/v in one launch
    qkv_kernel<<<dim3(DM/128, S/128, 3), 256>>>(p_h, Wq, bq, p_q, Wk, bk, p_k, Wv, bv, p_v);

    // 4. scores (into attn output region), 5. softmax in place
    scores_kernel<<<dim3(S/128, S/128, NH), 256>>>(p_q, p_k, attn);
    softmax_kernel<<<NH * S, 256>>>(attn);

    // 6. ctx = attn @ v
    ctx_kernel<<<dim3(S/128, NH), 128>>>(attn, p_v, p_ctx);

    // 7. mha = ctx @ Wo + bo
    sgemm_kernel<0,0><<<dim3(DM/128, S/128), 256>>>(p_ctx, Wo, bo, nullptr, p_mha, DM, DM);

    // 8. part1 = x + mha @ W2 + b2
    sgemm_kernel<0,1><<<dim3(DM/128, S/128), 256>>>(p_mha, W2, b2, x, p_part1, DM, DM);

    // 9. LN2
    ln_kernel<<<S, 256>>>(p_part1, g2, beta2, p_norm2);

    // 10. ff1 = relu(norm2 @ Wf1 + bf1)
    sgemm_kernel<1,0><<<dim3(DFF/128, S/128), 256>>>(p_norm2, Wf1, bf1, nullptr, p_ff1, DFF, DM);

    // 11. out = norm2 + ff1 @ Wf2 + bf2
    sgemm_kernel<0,1><<<dim3(DM/128, S/128), 256>>>(p_ff1, Wf2, bf2, p_norm2, out, DM, DFF);
}

// round 11
// speedup vs baseline: 1.5475x; 1.4787x over previous
#include <cuda_runtime.h>
#include <cuda_bf16.h>
#include <math.h>
#include <stdint.h>

#define S    2048
#define DM   1024
#define NH   16
#define DK   64
#define DFF  4096

// ---------------- scratch (device globals — no allocation allowed) ----------
__device__ float g_norm1[S * DM];
__device__ float g_h    [S * DM];
__device__ float g_q    [S * DM];
__device__ float g_k    [S * DM];
__device__ float g_v    [S * DM];
__device__ float g_ctx  [S * DM];
__device__ float g_mha  [S * DM];
__device__ float g_part1[S * DM];
__device__ float g_norm2[S * DM];
__device__ float g_ff1  [S * DFF];

// ================= helpers ===================================================
__device__ __forceinline__ uint32_t smem_u32(const void* p) {
    uint32_t a;
    asm("{ .reg .u64 t; cvta.to.shared.u64 t, %1; cvt.u32.u64 %0, t; }" : "=r"(a) : "l"(p));
    return a;
}

// fp32 -> (bf16 hi, bf16 lo) split
__device__ __forceinline__ void split2(float a, float b, uint32_t& hi, uint32_t& lo) {
    unsigned short ha = __bfloat16_as_ushort(__float2bfloat16_rn(a));
    unsigned short hb = __bfloat16_as_ushort(__float2bfloat16_rn(b));
    float fa = __bfloat162float(__ushort_as_bfloat16(ha));
    float fb = __bfloat162float(__ushort_as_bfloat16(hb));
    unsigned short la = __bfloat16_as_ushort(__float2bfloat16_rn(a - fa));
    unsigned short lb = __bfloat16_as_ushort(__float2bfloat16_rn(b - fb));
    hi = ((uint32_t)hb << 16) | ha;
    lo = ((uint32_t)lb << 16) | la;
}
__device__ __forceinline__ void split1(float a, unsigned short& h, unsigned short& l) {
    h = __bfloat16_as_ushort(__float2bfloat16_rn(a));
    l = __bfloat16_as_ushort(__float2bfloat16_rn(a - __bfloat162float(__ushort_as_bfloat16(h))));
}

__device__ __forceinline__ void ldsm_x4(uint32_t& a0, uint32_t& a1, uint32_t& a2, uint32_t& a3,
                                        uint32_t addr) {
    asm volatile("ldmatrix.sync.aligned.m8n8.x4.shared.b16 {%0,%1,%2,%3}, [%4];"
                 : "=r"(a0), "=r"(a1), "=r"(a2), "=r"(a3) : "r"(addr));
}
__device__ __forceinline__ void ldsm_x2(uint32_t& b0, uint32_t& b1, uint32_t addr) {
    asm volatile("ldmatrix.sync.aligned.m8n8.x2.shared.b16 {%0,%1}, [%2];"
                 : "=r"(b0), "=r"(b1) : "r"(addr));
}
__device__ __forceinline__ void mma16816(float* d, const uint32_t* a, const uint32_t* b) {
    asm volatile("mma.sync.aligned.m16n8k16.row.col.f32.bf16.bf16.f32 "
                 "{%0,%1,%2,%3}, {%4,%5,%6,%7}, {%8,%9}, {%0,%1,%2,%3};"
                 : "+f"(d[0]), "+f"(d[1]), "+f"(d[2]), "+f"(d[3])
                 : "r"(a[0]), "r"(a[1]), "r"(a[2]), "r"(a[3]), "r"(b[0]), "r"(b[1]));
}

// smem row pitch: 40 bf16 = 80 bytes (16B aligned rows; ldmatrix bank-conflict free)
#define PITCH 80

// ================= generic HMMA GEMM body ====================================
// C[128 x BN] = alpha * (A[128 x K] @ B) + bias + Dres, with 3xBF16 split.
// A: gmem [128][K] row-major (stride lda floats), tile-offset already applied.
// B: TRANSB ? gmem [K][...] rows (stride ldb), take BN cols  (transpose load)
//           : gmem [BN][K] K-major rows (stride ldb)          (direct load)
// C/Dres: tile-offset applied, stride ldc. bias: tile-offset applied (length BN).
template<int BN, int TRANSB, int HASBIAS, int RES, int RELU>
__device__ __forceinline__ void mma_gemm_body(
    const float* __restrict__ A, int lda,
    const float* __restrict__ B, int ldb,
    const float* __restrict__ bias, const float* __restrict__ Dres,
    float* __restrict__ C, int ldc, int K, float alpha)
{
    __shared__ __align__(128) char sAh[128 * PITCH];
    __shared__ __align__(128) char sAl[128 * PITCH];
    __shared__ __align__(128) char sBh[BN * PITCH];
    __shared__ __align__(128) char sBl[BN * PITCH];

    const int tid = threadIdx.x, lane = tid & 31, wid = tid >> 5;
    constexpr int WN  = (BN == 128) ? 4 : 2;     // warps along n
    constexpr int WM  = 8 / WN;                  // warps along m
    constexpr int WTM = 128 / WM;                // 64 or 32
    constexpr int WTN = BN / WN;                 // 32
    constexpr int MI  = WTM / 16;                // 4 or 2
    constexpr int NI  = WTN / 8;                 // 4
    const int wm = wid / WN, wn = wid % WN;

    float acc[MI][NI][4];
#pragma unroll
    for (int i = 0; i < MI; i++)
#pragma unroll
        for (int j = 0; j < NI; j++)
#pragma unroll
            for (int r = 0; r < 4; r++) acc[i][j][r] = 0.f;

    const int NCH = K >> 5;                      // BK = 32
    for (int c = 0; c < NCH; c++) {
        // ---- load A chunk: 128 rows x 32 k ----
#pragma unroll
        for (int i = 0; i < 4; i++) {
            int idx = i * 256 + tid;
            int r = idx >> 3, f = idx & 7;       // f: float4 within the 32-k row
            float4 v = *(const float4*)(A + (size_t)r * lda + (c << 5) + f * 4);
            uint32_t h0, l0, h1, l1;
            split2(v.x, v.y, h0, l0);
            split2(v.z, v.w, h1, l1);
            uint32_t o = (uint32_t)(r * PITCH + f * 8);
            *(uint2*)(sAh + o) = make_uint2(h0, h1);
            *(uint2*)(sAl + o) = make_uint2(l0, l1);
        }
        // ---- load B chunk ----
        if (TRANSB) {
            // B[k][*]: 32 k-rows, BN n-cols -> smem [n][k]
            if (BN == 128 || tid < 128) {
                int k4 = 4 * (lane & 7);
                int n  = 4 * (wid * 4 + (lane >> 3));
                const float* Bp = B + (size_t)((c << 5) + k4) * ldb + n;
                float4 q0 = *(const float4*)(Bp);
                float4 q1 = *(const float4*)(Bp + ldb);
                float4 q2 = *(const float4*)(Bp + 2 * (size_t)ldb);
                float4 q3 = *(const float4*)(Bp + 3 * (size_t)ldb);
                const float* f0 = &q0.x; const float* f1 = &q1.x;
                const float* f2 = &q2.x; const float* f3 = &q3.x;
#pragma unroll
                for (int j = 0; j < 4; j++) {
                    unsigned short h0, l0, h1, l1, h2, l2, h3, l3;
                    split1(f0[j], h0, l0);
                    split1(f1[j], h1, l1);
                    split1(f2[j], h2, l2);
                    split1(f3[j], h3, l3);
                    uint32_t o = (uint32_t)((n + j) * PITCH + k4 * 2);
                    *(uint2*)(sBh + o) =
                        make_uint2(((uint32_t)h1 << 16) | h0, ((uint32_t)h3 << 16) | h2);
                    *(uint2*)(sBl + o) =
                        make_uint2(((uint32_t)l1 << 16) | l0, ((uint32_t)l3 << 16) | l2);
                }
            }
        } else {
            // B[n][k] K-major: BN rows x 32 k (same pattern as A)
            constexpr int ITER = (BN * 8) / 256;
#pragma unroll
            for (int i = 0; i < ITER; i++) {
                int idx = i * 256 + tid;
                int r = idx >> 3, f = idx & 7;
                float4 v = *(const float4*)(B + (size_t)r * ldb + (c << 5) + f * 4);
                uint32_t h0, l0, h1, l1;
                split2(v.x, v.y, h0, l0);
                split2(v.z, v.w, h1, l1);
                uint32_t o = (uint32_t)(r * PITCH + f * 8);
                *(uint2*)(sBh + o) = make_uint2(h0, h1);
                *(uint2*)(sBl + o) = make_uint2(l0, l1);
            }
        }
        __syncthreads();

        // ---- compute: 2 k16-steps ----
#pragma unroll
        for (int ks = 0; ks < 2; ks++) {
            uint32_t Af[MI][4], Bhf[NI][2], Blf[NI][2];
            const int acol2 = (ks * 16 + ((lane >> 4) << 3)) * 2;
            const int bcol2 = (ks * 16 + (((lane >> 3) & 1) << 3)) * 2;
#pragma unroll
            for (int ni = 0; ni < NI; ni++) {
                uint32_t o = (uint32_t)((wn * WTN + ni * 8 + (lane & 7)) * PITCH + bcol2);
                ldsm_x2(Bhf[ni][0], Bhf[ni][1], smem_u32(sBh + o));
                ldsm_x2(Blf[ni][0], Blf[ni][1], smem_u32(sBl + o));
            }
#pragma unroll
            for (int mi = 0; mi < MI; mi++) {
                uint32_t o = (uint32_t)((wm * WTM + mi * 16 + (lane & 15)) * PITCH + acol2);
                ldsm_x4(Af[mi][0], Af[mi][1], Af[mi][2], Af[mi][3], smem_u32(sAh + o));
            }
#pragma unroll
            for (int mi = 0; mi < MI; mi++)
#pragma unroll
                for (int ni = 0; ni < NI; ni++) {
                    mma16816(acc[mi][ni], Af[mi], Bhf[ni]);   // hi * hi
                    mma16816(acc[mi][ni], Af[mi], Blf[ni]);   // hi * lo
                }
#pragma unroll
            for (int mi = 0; mi < MI; mi++) {
                uint32_t o = (uint32_t)((wm * WTM + mi * 16 + (lane & 15)) * PITCH + acol2);
                ldsm_x4(Af[mi][0], Af[mi][1], Af[mi][2], Af[mi][3], smem_u32(sAl + o));
            }
#pragma unroll
            for (int mi = 0; mi < MI; mi++)
#pragma unroll
                for (int ni = 0; ni < NI; ni++)
                    mma16816(acc[mi][ni], Af[mi], Bhf[ni]);   // lo * hi
        }
        __syncthreads();
    }

    // ---- epilogue ----
    const int groupID = lane >> 2, tig = lane & 3;
#pragma unroll
    for (int mi = 0; mi < MI; mi++) {
        const int r0 = wm * WTM + mi * 16 + groupID;
        const int r1 = r0 + 8;
#pragma unroll
        for (int ni = 0; ni < NI; ni++) {
            const int col = wn * WTN + ni * 8 + tig * 2;
            float2 v0, v1;
            v0.x = acc[mi][ni][0] * alpha; v0.y = acc[mi][ni][1] * alpha;
            v1.x = acc[mi][ni][2] * alpha; v1.y = acc[mi][ni][3] * alpha;
            if (HASBIAS) {
                v0.x += bias[col]; v0.y += bias[col + 1];
                v1.x += bias[col]; v1.y += bias[col + 1];
            }
            if (RES) {
                v0.x += Dres[(size_t)r0 * ldc + col];
                v0.y += Dres[(size_t)r0 * ldc + col + 1];
                v1.x += Dres[(size_t)r1 * ldc + col];
                v1.y += Dres[(size_t)r1 * ldc + col + 1];
            }
            if (RELU) {
                v0.x = fmaxf(v0.x, 0.f); v0.y = fmaxf(v0.y, 0.f);
                v1.x = fmaxf(v1.x, 0.f); v1.y = fmaxf(v1.y, 0.f);
            }
            *(float2*)(C + (size_t)r0 * ldc + col) = v0;
            *(float2*)(C + (size_t)r1 * ldc + col) = v1;
        }
    }
}

// ================= kernels ===================================================
template<int RELU, int RES>
__global__ void __launch_bounds__(256) mm_dense_kernel(
    const float* __restrict__ A, const float* __restrict__ W,
    const float* __restrict__ bias, const float* __restrict__ Dres,
    float* __restrict__ C, int N, int K)
{
    const int bm = blockIdx.y * 128, bn = blockIdx.x * 128;
    mma_gemm_body<128, 1, 1, RES, RELU>(
        A + (size_t)bm * K, K,
        W + bn, N,
        bias + bn,
        RES ? (Dres + (size_t)bm * N + bn) : (const float*)0,
        C + (size_t)bm * N + bn, N, K, 1.0f);
}

__global__ void __launch_bounds__(256) mm_qkv_kernel(
    const float* __restrict__ Hm,
    const float* __restrict__ Wq, const float* __restrict__ bq, float* __restrict__ Oq,
    const float* __restrict__ Wk, const float* __restrict__ bk, float* __restrict__ Ok,
    const float* __restrict__ Wv, const float* __restrict__ bv, float* __restrict__ Ov)
{
    const float* W; const float* b; float* O;
    if (blockIdx.z == 0)      { W = Wq; b = bq; O = Oq; }
    else if (blockIdx.z == 1) { W = Wk; b = bk; O = Ok; }
    else                      { W = Wv; b = bv; O = Ov; }
    const int bm = blockIdx.y * 128, bn = blockIdx.x * 128;
    mma_gemm_body<128, 1, 1, 0, 0>(
        Hm + (size_t)bm * DM, DM,
        W + bn, DM,
        b + bn, (const float*)0,
        O + (size_t)bm * DM + bn, DM, DM, 1.0f);
}

__global__ void __launch_bounds__(256) mm_scores_kernel(
    const float* __restrict__ Q, const float* __restrict__ Kc, float* __restrict__ P)
{
    const int kt = blockIdx.x, qt = blockIdx.y, h = blockIdx.z;
    if (kt > qt) return;     // fully-masked tile; softmax writes the zeros
    mma_gemm_body<128, 0, 0, 0, 0>(
        Q + (size_t)(qt * 128) * DM + h * DK, DM,
        Kc + (size_t)(kt * 128) * DM + h * DK, DM,
        (const float*)0, (const float*)0,
        P + (size_t)h * S * S + (size_t)(qt * 128) * S + kt * 128, S,
        DK, 0.125f);
}

__global__ void __launch_bounds__(256) mm_ctx_kernel(
    const float* __restrict__ P, const float* __restrict__ V, float* __restrict__ Cx)
{
    const int qt = blockIdx.x, h = blockIdx.y;
    mma_gemm_body<64, 1, 0, 0, 0>(
        P + (size_t)h * S * S + (size_t)(qt * 128) * S, S,
        V + h * DK, DM,
        (const float*)0, (const float*)0,
        Cx + (size_t)(qt * 128) * DM + h * DK, DM,
        (qt + 1) * 128, 1.0f);
}

// ================= LN / softmax (memory-bound) ===============================
__device__ __forceinline__ float warp_sum(float v) {
#pragma unroll
    for (int o = 16; o > 0; o >>= 1) v += __shfl_xor_sync(0xffffffffu, v, o);
    return v;
}
__device__ __forceinline__ float warp_max(float v) {
#pragma unroll
    for (int o = 16; o > 0; o >>= 1) v = fmaxf(v, __shfl_xor_sync(0xffffffffu, v, o));
    return v;
}
__device__ __forceinline__ float block_sum(float v, float* red) {
    const int tid = threadIdx.x;
    v = warp_sum(v);
    if ((tid & 31) == 0) red[tid >> 5] = v;
    __syncthreads();
    float r = (tid < 8) ? red[tid] : 0.f;
    r = warp_sum(r);
    if (tid == 0) red[0] = r;
    __syncthreads();
    return red[0];
}
__device__ __forceinline__ float block_max(float v, float* red) {
    const int tid = threadIdx.x;
    v = warp_max(v);
    if ((tid & 31) == 0) red[tid >> 5] = v;
    __syncthreads();
    float r = (tid < 8) ? red[tid] : -3.0e38f;
    r = warp_max(r);
    if (tid == 0) red[0] = r;
    __syncthreads();
    return red[0];
}

__global__ void __launch_bounds__(256) ln_kernel(const float* __restrict__ x,
                                                 const float* __restrict__ g,
                                                 const float* __restrict__ b,
                                                 float* __restrict__ y)
{
    const int row = blockIdx.x;
    const float4* xr = (const float4*)(x + (size_t)row * DM);
    float4* yr = (float4*)(y + (size_t)row * DM);
    __shared__ float red[8];
    const int tid = threadIdx.x;

    float4 xv = xr[tid];
    float s = xv.x + xv.y + xv.z + xv.w;
    const float mean = block_sum(s, red) * (1.f / DM);
    __syncthreads();

    float dx = xv.x - mean, dy = xv.y - mean, dz = xv.z - mean, dw = xv.w - mean;
    float v = dx * dx + dy * dy + dz * dz + dw * dw;
    const float var = block_sum(v, red) * (1.f / DM);
    const float inv = 1.f / (sqrtf(var) + 1e-6f);

    float4 gv = ((const float4*)g)[tid];
    float4 bv = ((const float4*)b)[tid];
    float4 o;
    o.x = gv.x * (dx * inv) + bv.x;
    o.y = gv.y * (dy * inv) + bv.y;
    o.z = gv.z * (dz * inv) + bv.z;
    o.w = gv.w * (dw * inv) + bv.w;
    yr[tid] = o;
}

__global__ void __launch_bounds__(256) softmax_kernel(float* __restrict__ P)
{
    const int row = blockIdx.x;          // h*S + q
    const int qi = row & (S - 1);
    float* p = P + (size_t)row * S;
    const int n = qi + 1;
    __shared__ float red[8];
    const int tid = threadIdx.x;

    float m = -3.0e38f;
    for (int j = tid; j < n; j += 256) m = fmaxf(m, p[j]);
    m = block_max(m, red);
    __syncthreads();

    float sum = 0.f;
    for (int j = tid; j < n; j += 256) { float e = expf(p[j] - m); p[j] = e; sum += e; }
    sum = block_sum(sum, red);
    const float inv = 1.f / sum;

    for (int j = tid; j < n; j += 256) p[j] *= inv;
    for (int j = n + tid; j < S; j += 256) p[j] = 0.f;
}

// ================= host orchestration ========================================
extern "C" void kernel_launch(void* const* d_in, const int* in_sizes, int n_in,
                              void* d_out, int out_size)
{
    const float* x     = (const float*)d_in[0];
    const float* g1    = (const float*)d_in[1];
    const float* beta1 = (const float*)d_in[2];
    const float* W_in  = (const float*)d_in[3];
    const float* b_in  = (const float*)d_in[4];
    const float* Wq    = (const float*)d_in[5];
    const float* bq    = (const float*)d_in[6];
    const float* Wk    = (const float*)d_in[7];
    const float* bk    = (const float*)d_in[8];
    const float* Wv    = (const float*)d_in[9];
    const float* bv    = (const float*)d_in[10];
    const float* Wo    = (const float*)d_in[11];
    const float* bo    = (const float*)d_in[12];
    const float* W2    = (const float*)d_in[13];
    const float* b2    = (const float*)d_in[14];
    const float* g2    = (const float*)d_in[15];
    const float* beta2 = (const float*)d_in[16];
    const float* Wf1   = (const float*)d_in[17];
    const float* bf1   = (const float*)d_in[18];
    const float* Wf2   = (const float*)d_in[19];
    const float* bf2   = (const float*)d_in[20];

    float* out  = (float*)d_out;                       // [S, DM]
    float* attn = (float*)d_out + (size_t)S * DM;      // [NH, S, S]

    float *p_norm1, *p_h, *p_q, *p_k, *p_v, *p_ctx, *p_mha, *p_part1, *p_norm2, *p_ff1;
    cudaGetSymbolAddress((void**)&p_norm1, g_norm1);
    cudaGetSymbolAddress((void**)&p_h,     g_h);
    cudaGetSymbolAddress((void**)&p_q,     g_q);
    cudaGetSymbolAddress((void**)&p_k,     g_k);
    cudaGetSymbolAddress((void**)&p_v,     g_v);
    cudaGetSymbolAddress((void**)&p_ctx,   g_ctx);
    cudaGetSymbolAddress((void**)&p_mha,   g_mha);
    cudaGetSymbolAddress((void**)&p_part1, g_part1);
    cudaGetSymbolAddress((void**)&p_norm2, g_norm2);
    cudaGetSymbolAddress((void**)&p_ff1,   g_ff1);

    // 1. LN1
    ln_kernel<<<S, 256>>>(x, g1, beta1, p_norm1);

    // 2. h = norm1 @ W_in + b_in
    mm_dense_kernel<0,0><<<dim3(DM/128, S/128), 256>>>(p_norm1, W_in, b_in, nullptr, p_h, DM, DM);

    // 3. q/k/v in one launch
    mm_qkv_kernel<<<dim3(DM/128, S/128, 3), 256>>>(p_h, Wq, bq, p_q, Wk, bk, p_k, Wv, bv, p_v);

    // 4. scores (into attn output region), 5. softmax in place
    mm_scores_kernel<<<dim3(S/128, S/128, NH), 256>>>(p_q, p_k, attn);
    softmax_kernel<<<NH * S, 256>>>(attn);

    // 6. ctx = attn @ v
    mm_ctx_kernel<<<dim3(S/128, NH), 256>>>(attn, p_v, p_ctx);

    // 7. mha = ctx @ Wo + bo
    mm_dense_kernel<0,0><<<dim3(DM/128, S/128), 256>>>(p_ctx, Wo, bo, nullptr, p_mha, DM, DM);

    // 8. part1 = x + mha @ W2 + b2
    mm_dense_kernel<0,1><<<dim3(DM/128, S/128), 256>>>(p_mha, W2, b2, x, p_part1, DM, DM);

    // 9. LN2
    ln_kernel<<<S, 256>>>(p_part1, g2, beta2, p_norm2);

    // 10. ff1 = relu(norm2 @ Wf1 + bf1)
    mm_dense_kernel<1,0><<<dim3(DFF/128, S/128), 256>>>(p_norm2, Wf1, bf1, nullptr, p_ff1, DFF, DM);

    // 11. out = norm2 + ff1 @ Wf2 + bf2
    mm_dense_kernel<0,1><<<dim3(DM/128, S/128), 256>>>(p_ff1, Wf2, bf2, p_norm2, out, DM, DFF);
}

// round 12
// speedup vs baseline: 2.4976x; 1.6140x over previous
#include <cuda_runtime.h>
#include <cuda_bf16.h>
#include <math.h>
#include <stdint.h>

#define S    2048
#define DM   1024
#define NH   16
#define DK   64
#define DFF  4096

typedef __nv_bfloat16 bf;

// ---------------- fp32 scratch (only where fp32 is actually consumed) -------
__device__ float g_part1[S * DM];
__device__ float g_norm2[S * DM];

// ---------------- bf16 hi/lo scratch ----------------------------------------
#define DECL2(name, n) __device__ __align__(128) bf name##h[n]; __device__ __align__(128) bf name##l[n];
DECL2(g_n1,  S * DM)
DECL2(g_hv,  S * DM)
DECL2(g_q,   S * DM)
DECL2(g_k,   S * DM)
DECL2(g_v,   S * DM)
DECL2(g_vt,  S * DM)          // [NH][DK][S]
DECL2(g_ctx, S * DM)
DECL2(g_mha, S * DM)
DECL2(g_n2,  S * DM)
DECL2(g_f1,  S * DFF)
DECL2(g_p,   (size_t)NH * S * S)
// weights (K-major [N][K])
DECL2(g_wIn, DM * DM)
DECL2(g_wQ,  DM * DM)
DECL2(g_wK,  DM * DM)
DECL2(g_wV,  DM * DM)
DECL2(g_wO,  DM * DM)
DECL2(g_w2,  DM * DM)
DECL2(g_wF1, DM * DFF)
DECL2(g_wF2, DFF * DM)

// ================= helpers ===================================================
__device__ __forceinline__ uint32_t smem_u32(const void* p) {
    uint32_t a;
    asm("{ .reg .u64 t; cvta.to.shared.u64 t, %1; cvt.u32.u64 %0, t; }" : "=r"(a) : "l"(p));
    return a;
}
__device__ __forceinline__ void split2(float a, float b, uint32_t& hi, uint32_t& lo) {
    unsigned short ha = __bfloat16_as_ushort(__float2bfloat16_rn(a));
    unsigned short hb = __bfloat16_as_ushort(__float2bfloat16_rn(b));
    float fa = __bfloat162float(__ushort_as_bfloat16(ha));
    float fb = __bfloat162float(__ushort_as_bfloat16(hb));
    unsigned short la = __bfloat16_as_ushort(__float2bfloat16_rn(a - fa));
    unsigned short lb = __bfloat16_as_ushort(__float2bfloat16_rn(b - fb));
    hi = ((uint32_t)hb << 16) | ha;
    lo = ((uint32_t)lb << 16) | la;
}
__device__ __forceinline__ void split1(float a, unsigned short& h, unsigned short& l) {
    h = __bfloat16_as_ushort(__float2bfloat16_rn(a));
    l = __bfloat16_as_ushort(__float2bfloat16_rn(a - __bfloat162float(__ushort_as_bfloat16(h))));
}
__device__ __forceinline__ void ldsm_x4(uint32_t& a0, uint32_t& a1, uint32_t& a2, uint32_t& a3,
                                        uint32_t addr) {
    asm volatile("ldmatrix.sync.aligned.m8n8.x4.shared.b16 {%0,%1,%2,%3}, [%4];"
                 : "=r"(a0), "=r"(a1), "=r"(a2), "=r"(a3) : "r"(addr));
}
__device__ __forceinline__ void ldsm_x2(uint32_t& b0, uint32_t& b1, uint32_t addr) {
    asm volatile("ldmatrix.sync.aligned.m8n8.x2.shared.b16 {%0,%1}, [%2];"
                 : "=r"(b0), "=r"(b1) : "r"(addr));
}
__device__ __forceinline__ void mma16816(float* d, const uint32_t* a, const uint32_t* b) {
    asm volatile("mma.sync.aligned.m16n8k16.row.col.f32.bf16.bf16.f32 "
                 "{%0,%1,%2,%3}, {%4,%5,%6,%7}, {%8,%9}, {%0,%1,%2,%3};"
                 : "+f"(d[0]), "+f"(d[1]), "+f"(d[2]), "+f"(d[3])
                 : "r"(a[0]), "r"(a[1]), "r"(a[2]), "r"(a[3]), "r"(b[0]), "r"(b[1]));
}
__device__ __forceinline__ void cpa16(uint32_t saddr, const void* g) {
    asm volatile("cp.async.ca.shared.global [%0], [%1], 16;" :: "r"(saddr), "l"(g));
}
#define CP_COMMIT() asm volatile("cp.async.commit_group;" ::: "memory")

#define PITCH 80   // bytes per smem row (32 bf16 data + pad); ldmatrix conflict-free

// ================= pipelined HMMA GEMM body ==================================
// C[128 x BN] = alpha*(A@B) (+bias)(+res)(+relu); A/B from pre-split bf16 hi/lo,
// both K-major (rows of lda/ldb bf16 elems; chunk = 32 k). 2-stage cp.async.
template<int BN, int HASBIAS, int RES, int RELU, int WF32, int WSPLIT>
__device__ __forceinline__ void mma_body(
    const bf* __restrict__ Ah, const bf* __restrict__ Al, int lda,
    const bf* __restrict__ Bh, const bf* __restrict__ Bl, int ldb,
    const float* __restrict__ bias, const float* __restrict__ Dres,
    float* __restrict__ C, bf* __restrict__ Ch, bf* __restrict__ Cl,
    int ldc, int K, float alpha)
{
    extern __shared__ __align__(128) char sm[];
    constexpr int ASZ = 128 * PITCH;           // 10240
    constexpr int BSZ = BN * PITCH;
    constexpr int STAGE = 2 * ASZ + 2 * BSZ;

    const int tid = threadIdx.x, lane = tid & 31, wid = tid >> 5;
    constexpr int WN  = (BN == 128) ? 4 : 2;
    constexpr int WM  = 8 / WN;
    constexpr int WTM = 128 / WM;
    constexpr int WTN = BN / WN;
    constexpr int MI  = WTM / 16;
    constexpr int NI  = WTN / 8;
    const int wm = wid / WN, wn = wid % WN;
    const uint32_t sb = smem_u32(sm);

    float acc[MI][NI][4];
#pragma unroll
    for (int i = 0; i < MI; i++)
#pragma unroll
        for (int j = 0; j < NI; j++)
#pragma unroll
            for (int r = 0; r < 4; r++) acc[i][j][r] = 0.f;

    const int NC = K >> 5;

    auto issue = [&](int st, int c) {
        const uint32_t base = sb + st * STAGE;
        // A: 128 rows x 4 segs x {hi,lo} = 1024 cp.async / 256 thr
#pragma unroll
        for (int it = 0; it < 4; it++) {
            int idx = it * 256 + tid;
            int arr = idx >> 9;                 // 0,0,1,1
            int rem = idx & 511;
            int r = rem >> 2, sg = rem & 3;
            const bf* g = (arr ? Al : Ah) + (size_t)r * lda + (size_t)c * 32 + sg * 8;
            cpa16(base + arr * ASZ + r * PITCH + sg * 16, g);
        }
        // B: BN rows x 4 segs x {hi,lo}
#pragma unroll
        for (int it = 0; it < BN / 32; it++) {
            int idx = it * 256 + tid;
            int arr = idx / (BN * 4);
            int rem = idx % (BN * 4);
            int r = rem >> 2, sg = rem & 3;
            const bf* g = (arr ? Bl : Bh) + (size_t)r * ldb + (size_t)c * 32 + sg * 8;
            cpa16(base + 2 * ASZ + arr * BSZ + r * PITCH + sg * 16, g);
        }
    };

    issue(0, 0);
    CP_COMMIT();

    for (int c = 0; c < NC; c++) {
        const int st = c & 1;
        const bool pf = (c + 1 < NC);
        if (pf) { issue(st ^ 1, c + 1); CP_COMMIT(); }
        if (pf) { asm volatile("cp.async.wait_group 1;" ::: "memory"); }
        else    { asm volatile("cp.async.wait_group 0;" ::: "memory"); }
        __syncthreads();

        const uint32_t aH = sb + st * STAGE;
        const uint32_t aL = aH + ASZ;
        const uint32_t bH = aH + 2 * ASZ;
        const uint32_t bL = bH + BSZ;

#pragma unroll
        for (int ks = 0; ks < 2; ks++) {
            uint32_t Af[MI][4], Bhf[NI][2], Blf[NI][2];
            const int acol2 = (ks * 16 + ((lane >> 4) << 3)) * 2;
            const int bcol2 = (ks * 16 + (((lane >> 3) & 1) << 3)) * 2;
#pragma unroll
            for (int ni = 0; ni < NI; ni++) {
                uint32_t o = (uint32_t)((wn * WTN + ni * 8 + (lane & 7)) * PITCH + bcol2);
                ldsm_x2(Bhf[ni][0], Bhf[ni][1], bH + o);
                ldsm_x2(Blf[ni][0], Blf[ni][1], bL + o);
            }
#pragma unroll
            for (int mi = 0; mi < MI; mi++) {
                uint32_t o = (uint32_t)((wm * WTM + mi * 16 + (lane & 15)) * PITCH + acol2);
                ldsm_x4(Af[mi][0], Af[mi][1], Af[mi][2], Af[mi][3], aH + o);
            }
#pragma unroll
            for (int mi = 0; mi < MI; mi++)
#pragma unroll
                for (int ni = 0; ni < NI; ni++) {
                    mma16816(acc[mi][ni], Af[mi], Bhf[ni]);   // hi*hi
                    mma16816(acc[mi][ni], Af[mi], Blf[ni]);   // hi*lo
                }
#pragma unroll
            for (int mi = 0; mi < MI; mi++) {
                uint32_t o = (uint32_t)((wm * WTM + mi * 16 + (lane & 15)) * PITCH + acol2);
                ldsm_x4(Af[mi][0], Af[mi][1], Af[mi][2], Af[mi][3], aL + o);
            }
#pragma unroll
            for (int mi = 0; mi < MI; mi++)
#pragma unroll
                for (int ni = 0; ni < NI; ni++)
                    mma16816(acc[mi][ni], Af[mi], Bhf[ni]);   // lo*hi
        }
        __syncthreads();
    }

    // ---- epilogue ----
    const int groupID = lane >> 2, tig = lane & 3;
#pragma unroll
    for (int mi = 0; mi < MI; mi++) {
        const int r0 = wm * WTM + mi * 16 + groupID;
        const int r1 = r0 + 8;
#pragma unroll
        for (int ni = 0; ni < NI; ni++) {
            const int col = wn * WTN + ni * 8 + tig * 2;
            float2 v0, v1;
            v0.x = acc[mi][ni][0] * alpha; v0.y = acc[mi][ni][1] * alpha;
            v1.x = acc[mi][ni][2] * alpha; v1.y = acc[mi][ni][3] * alpha;
            if (HASBIAS) {
                v0.x += bias[col]; v0.y += bias[col + 1];
                v1.x += bias[col]; v1.y += bias[col + 1];
            }
            if (RES) {
                v0.x += Dres[(size_t)r0 * ldc + col];
                v0.y += Dres[(size_t)r0 * ldc + col + 1];
                v1.x += Dres[(size_t)r1 * ldc + col];
                v1.y += Dres[(size_t)r1 * ldc + col + 1];
            }
            if (RELU) {
                v0.x = fmaxf(v0.x, 0.f); v0.y = fmaxf(v0.y, 0.f);
                v1.x = fmaxf(v1.x, 0.f); v1.y = fmaxf(v1.y, 0.f);
            }
            if (WF32) {
                *(float2*)(C + (size_t)r0 * ldc + col) = v0;
                *(float2*)(C + (size_t)r1 * ldc + col) = v1;
            }
            if (WSPLIT) {
                uint32_t hi, lo;
                split2(v0.x, v0.y, hi, lo);
                *(uint32_t*)(Ch + (size_t)r0 * ldc + col) = hi;
                *(uint32_t*)(Cl + (size_t)r0 * ldc + col) = lo;
                split2(v1.x, v1.y, hi, lo);
                *(uint32_t*)(Ch + (size_t)r1 * ldc + col) = hi;
                *(uint32_t*)(Cl + (size_t)r1 * ldc + col) = lo;
            }
        }
    }
}

// ================= GEMM kernels ==============================================
template<int RES, int RELU, int WF32, int WSPLIT>
__global__ void __launch_bounds__(256, 2) mm_dense_kernel(
    const bf* __restrict__ Ah, const bf* __restrict__ Al,
    const bf* __restrict__ Bh, const bf* __restrict__ Bl,
    const float* __restrict__ bias, const float* __restrict__ Dres,
    float* __restrict__ C, bf* __restrict__ Ch, bf* __restrict__ Cl,
    int N, int K)
{
    const int bm = blockIdx.y * 128, bn = blockIdx.x * 128;
    mma_body<128, 1, RES, RELU, WF32, WSPLIT>(
        Ah + (size_t)bm * K, Al + (size_t)bm * K, K,
        Bh + (size_t)bn * K, Bl + (size_t)bn * K, K,
        bias + bn,
        RES ? (Dres + (size_t)bm * N + bn) : (const float*)0,
        WF32 ? (C + (size_t)bm * N + bn) : (float*)0,
        WSPLIT ? (Ch + (size_t)bm * N + bn) : (bf*)0,
        WSPLIT ? (Cl + (size_t)bm * N + bn) : (bf*)0,
        N, K, 1.0f);
}

__global__ void __launch_bounds__(256, 2) mm_qkv_kernel(
    const bf* __restrict__ Hh, const bf* __restrict__ Hl,
    const bf* __restrict__ WQh, const bf* __restrict__ WQl, const float* __restrict__ bq,
    bf* __restrict__ Qh, bf* __restrict__ Ql,
    const bf* __restrict__ WKh, const bf* __restrict__ WKl, const float* __restrict__ bk,
    bf* __restrict__ Kh, bf* __restrict__ Kl,
    const bf* __restrict__ WVh, const bf* __restrict__ WVl, const float* __restrict__ bv,
    bf* __restrict__ Vh, bf* __restrict__ Vl)
{
    const bf *Wh, *Wl; const float* b; bf *Oh, *Ol;
    if (blockIdx.z == 0)      { Wh = WQh; Wl = WQl; b = bq; Oh = Qh; Ol = Ql; }
    else if (blockIdx.z == 1) { Wh = WKh; Wl = WKl; b = bk; Oh = Kh; Ol = Kl; }
    else                      { Wh = WVh; Wl = WVl; b = bv; Oh = Vh; Ol = Vl; }
    const int bm = blockIdx.y * 128, bn = blockIdx.x * 128;
    mma_body<128, 1, 0, 0, 0, 1>(
        Hh + (size_t)bm * DM, Hl + (size_t)bm * DM, DM,
        Wh + (size_t)bn * DM, Wl + (size_t)bn * DM, DM,
        b + bn, (const float*)0,
        (float*)0,
        Oh + (size_t)bm * DM + bn, Ol + (size_t)bm * DM + bn,
        DM, DM, 1.0f);
}

__global__ void __launch_bounds__(256, 2) mm_scores_kernel(
    const bf* __restrict__ Qh, const bf* __restrict__ Ql,
    const bf* __restrict__ Kh, const bf* __restrict__ Kl,
    float* __restrict__ P)
{
    const int kt = blockIdx.x, qt = blockIdx.y, h = blockIdx.z;
    if (kt > qt) return;
    mma_body<128, 0, 0, 0, 1, 0>(
        Qh + (size_t)(qt * 128) * DM + h * DK, Ql + (size_t)(qt * 128) * DM + h * DK, DM,
        Kh + (size_t)(kt * 128) * DM + h * DK, Kl + (size_t)(kt * 128) * DM + h * DK, DM,
        (const float*)0, (const float*)0,
        P + (size_t)h * S * S + (size_t)(qt * 128) * S + kt * 128,
        (bf*)0, (bf*)0, S, DK, 0.125f);
}

__global__ void __launch_bounds__(256, 2) mm_ctx_kernel(
    const bf* __restrict__ Ph, const bf* __restrict__ Pl,
    const bf* __restrict__ Vth, const bf* __restrict__ Vtl,
    bf* __restrict__ Ch, bf* __restrict__ Cl)
{
    const int qt = blockIdx.x, h = blockIdx.y;
    mma_body<64, 0, 0, 0, 0, 1>(
        Ph + (size_t)h * S * S + (size_t)(qt * 128) * S,
        Pl + (size_t)h * S * S + (size_t)(qt * 128) * S, S,
        Vth + (size_t)h * DK * S, Vtl + (size_t)h * DK * S, S,
        (const float*)0, (const float*)0,
        (float*)0,
        Ch + (size_t)(qt * 128) * DM + h * DK, Cl + (size_t)(qt * 128) * DM + h * DK,
        DM, (qt + 1) * 128, 1.0f);
}

// ================= prep kernels ==============================================
// weights: W[K][N] fp32 -> Bh/Bl[N][K] bf16 (32x32 smem transpose)
__global__ void __launch_bounds__(256) prep_w_kernel(
    const float* __restrict__ W, bf* __restrict__ Bh, bf* __restrict__ Bl, int N, int K)
{
    __shared__ float t[32][33];
    const int n0 = blockIdx.x * 32, k0 = blockIdx.y * 32;
    const int tx = threadIdx.x & 31, ty = threadIdx.x >> 5;
#pragma unroll
    for (int i = 0; i < 4; i++) {
        int k = ty + i * 8;
        t[k][tx] = W[(size_t)(k0 + k) * N + n0 + tx];
    }
    __syncthreads();
#pragma unroll
    for (int i = 0; i < 4; i++) {
        int n = ty + i * 8;
        float v = t[tx][n];
        unsigned short h, l;
        split1(v, h, l);
        size_t o = (size_t)(n0 + n) * K + k0 + tx;
        Bh[o] = __ushort_as_bfloat16(h);
        Bl[o] = __ushort_as_bfloat16(l);
    }
}

// vt[h][c][s] = v[s][h*64+c] (bf16 transpose, hi & lo)
__global__ void __launch_bounds__(256) prep_vt_kernel(
    const bf* __restrict__ Vh, const bf* __restrict__ Vl,
    bf* __restrict__ Vth, bf* __restrict__ Vtl)
{
    __shared__ bf th[32][33], tl[32][33];
    const int s0 = blockIdx.x * 32, c0 = blockIdx.y * 32, h = blockIdx.z;
    const int tx = threadIdx.x & 31, ty = threadIdx.x >> 5;
#pragma unroll
    for (int i = 0; i < 4; i++) {
        int s = ty + i * 8;
        th[s][tx] = Vh[(size_t)(s0 + s) * DM + h * DK + c0 + tx];
        tl[s][tx] = Vl[(size_t)(s0 + s) * DM + h * DK + c0 + tx];
    }
    __syncthreads();
#pragma unroll
    for (int i = 0; i < 4; i++) {
        int cc = ty + i * 8;
        size_t o = ((size_t)h * DK + c0 + cc) * S + s0 + tx;
        Vth[o] = th[tx][cc];
        Vtl[o] = tl[tx][cc];
    }
}

// ================= LN / softmax ==============================================
__device__ __forceinline__ float warp_sum(float v) {
#pragma unroll
    for (int o = 16; o > 0; o >>= 1) v += __shfl_xor_sync(0xffffffffu, v, o);
    return v;
}
__device__ __forceinline__ float warp_max(float v) {
#pragma unroll
    for (int o = 16; o > 0; o >>= 1) v = fmaxf(v, __shfl_xor_sync(0xffffffffu, v, o));
    return v;
}
__device__ __forceinline__ float block_sum(float v, float* red) {
    const int tid = threadIdx.x;
    v = warp_sum(v);
    if ((tid & 31) == 0) red[tid >> 5] = v;
    __syncthreads();
    float r = (tid < 8) ? red[tid] : 0.f;
    r = warp_sum(r);
    if (tid == 0) red[0] = r;
    __syncthreads();
    return red[0];
}
__device__ __forceinline__ float block_max(float v, float* red) {
    const int tid = threadIdx.x;
    v = warp_max(v);
    if ((tid & 31) == 0) red[tid >> 5] = v;
    __syncthreads();
    float r = (tid < 8) ? red[tid] : -3.0e38f;
    r = warp_max(r);
    if (tid == 0) red[0] = r;
    __syncthreads();
    return red[0];
}

template<int WF32>
__global__ void __launch_bounds__(256) ln_kernel(
    const float* __restrict__ x, const float* __restrict__ g, const float* __restrict__ b,
    float* __restrict__ y, bf* __restrict__ yh, bf* __restrict__ yl)
{
    const int row = blockIdx.x;
    const float4* xr = (const float4*)(x + (size_t)row * DM);
    __shared__ float red[8];
    const int tid = threadIdx.x;

    float4 xv = xr[tid];
    float s = xv.x + xv.y + xv.z + xv.w;
    const float mean = block_sum(s, red) * (1.f / DM);
    __syncthreads();

    float dx = xv.x - mean, dy = xv.y - mean, dz = xv.z - mean, dw = xv.w - mean;
    float v = dx * dx + dy * dy + dz * dz + dw * dw;
    const float var = block_sum(v, red) * (1.f / DM);
    const float inv = 1.f / (sqrtf(var) + 1e-6f);

    float4 gv = ((const float4*)g)[tid];
    float4 bv = ((const float4*)b)[tid];
    float4 o;
    o.x = gv.x * (dx * inv) + bv.x;
    o.y = gv.y * (dy * inv) + bv.y;
    o.z = gv.z * (dz * inv) + bv.z;
    o.w = gv.w * (dw * inv) + bv.w;
    if (WF32) ((float4*)(y + (size_t)row * DM))[tid] = o;

    uint32_t h0, l0, h1, l1;
    split2(o.x, o.y, h0, l0);
    split2(o.z, o.w, h1, l1);
    *(uint2*)(yh + (size_t)row * DM + tid * 4) = make_uint2(h0, h1);
    *(uint2*)(yl + (size_t)row * DM + tid * 4) = make_uint2(l0, l1);
}

__global__ void __launch_bounds__(256) softmax_kernel(
    float* __restrict__ P, bf* __restrict__ Ph, bf* __restrict__ Pl)
{
    const int row = blockIdx.x;          // h*S + q
    const int qi = row & (S - 1);
    float* p = P + (size_t)row * S;
    bf* ph = Ph + (size_t)row * S;
    bf* pl = Pl + (size_t)row * S;
    const int n = qi + 1;
    __shared__ float red[8];
    const int tid = threadIdx.x;

    float m = -3.0e38f;
    for (int j = tid; j < n; j += 256) m = fmaxf(m, p[j]);
    m = block_max(m, red);
    __syncthreads();

    float sum = 0.f;
    for (int j = tid; j < n; j += 256) { float e = expf(p[j] - m); p[j] = e; sum += e; }
    sum = block_sum(sum, red);
    const float inv = 1.f / sum;

    for (int j = tid; j < n; j += 256) {
        float val = p[j] * inv;
        p[j] = val;
        unsigned short h, l;
        split1(val, h, l);
        ph[j] = __ushort_as_bfloat16(h);
        pl[j] = __ushort_as_bfloat16(l);
    }
    const bf z = __ushort_as_bfloat16(0);
    for (int j = n + tid; j < S; j += 256) { p[j] = 0.f; ph[j] = z; pl[j] = z; }
}

// ================= host orchestration ========================================
#define GETP(var, sym) cudaGetSymbolAddress((void**)&var, sym)

extern "C" void kernel_launch(void* const* d_in, const int* in_sizes, int n_in,
                              void* d_out, int out_size)
{
    const float* x     = (const float*)d_in[0];
    const float* g1    = (const float*)d_in[1];
    const float* beta1 = (const float*)d_in[2];
    const float* W_in  = (const float*)d_in[3];
    const float* b_in  = (const float*)d_in[4];
    const float* Wq    = (const float*)d_in[5];
    const float* bq    = (const float*)d_in[6];
    const float* Wk    = (const float*)d_in[7];
    const float* bk    = (const float*)d_in[8];
    const float* Wv    = (const float*)d_in[9];
    const float* bv    = (const float*)d_in[10];
    const float* Wo    = (const float*)d_in[11];
    const float* bo    = (const float*)d_in[12];
    const float* W2    = (const float*)d_in[13];
    const float* b2    = (const float*)d_in[14];
    const float* g2    = (const float*)d_in[15];
    const float* beta2 = (const float*)d_in[16];
    const float* Wf1   = (const float*)d_in[17];
    const float* bf1   = (const float*)d_in[18];
    const float* Wf2   = (const float*)d_in[19];
    const float* bf2   = (const float*)d_in[20];

    float* out  = (float*)d_out;                       // [S, DM]
    float* attn = (float*)d_out + (size_t)S * DM;      // [NH, S, S]

    float *p_part1, *p_norm2;
    GETP(p_part1, g_part1); GETP(p_norm2, g_norm2);

    bf *n1h, *n1l, *hh, *hl, *qh, *ql, *kh, *kl, *vh, *vl, *vth, *vtl;
    bf *ctxh, *ctxl, *mhah, *mhal, *n2h, *n2l, *f1h, *f1l, *pph, *ppl;
    GETP(n1h, g_n1h); GETP(n1l, g_n1l);
    GETP(hh, g_hvh);  GETP(hl, g_hvl);
    GETP(qh, g_qh);   GETP(ql, g_ql);
    GETP(kh, g_kh);   GETP(kl, g_kl);
    GETP(vh, g_vh);   GETP(vl, g_vl);
    GETP(vth, g_vth); GETP(vtl, g_vtl);
    GETP(ctxh, g_ctxh); GETP(ctxl, g_ctxl);
    GETP(mhah, g_mhah); GETP(mhal, g_mhal);
    GETP(n2h, g_n2h); GETP(n2l, g_n2l);
    GETP(f1h, g_f1h); GETP(f1l, g_f1l);
    GETP(pph, g_ph);  GETP(ppl, g_pl);

    bf *wInh, *wInl, *wQh, *wQl, *wKh, *wKl, *wVh, *wVl, *wOh, *wOl, *w2h, *w2l;
    bf *wF1h, *wF1l, *wF2h, *wF2l;
    GETP(wInh, g_wInh); GETP(wInl, g_wInl);
    GETP(wQh, g_wQh);   GETP(wQl, g_wQl);
    GETP(wKh, g_wKh);   GETP(wKl, g_wKl);
    GETP(wVh, g_wVh);   GETP(wVl, g_wVl);
    GETP(wOh, g_wOh);   GETP(wOl, g_wOl);
    GETP(w2h, g_w2h);   GETP(w2l, g_w2l);
    GETP(wF1h, g_wF1h); GETP(wF1l, g_wF1l);
    GETP(wF2h, g_wF2h); GETP(wF2l, g_wF2l);

    // dynamic smem opt-in (capture-safe, deterministic)
    const int SM128 = 2 * (2 * 128 * PITCH + 2 * 128 * PITCH);   // 81920
    const int SM64  = 2 * (2 * 128 * PITCH + 2 * 64 * PITCH);    // 61440
    cudaFuncSetAttribute(mm_dense_kernel<0,0,0,1>, cudaFuncAttributeMaxDynamicSharedMemorySize, SM128);
    cudaFuncSetAttribute(mm_dense_kernel<1,0,1,0>, cudaFuncAttributeMaxDynamicSharedMemorySize, SM128);
    cudaFuncSetAttribute(mm_dense_kernel<0,1,0,1>, cudaFuncAttributeMaxDynamicSharedMemorySize, SM128);
    cudaFuncSetAttribute(mm_dense_kernel<1,0,1,1>, cudaFuncAttributeMaxDynamicSharedMemorySize, SM128);
    cudaFuncSetAttribute(mm_qkv_kernel,    cudaFuncAttributeMaxDynamicSharedMemorySize, SM128);
    cudaFuncSetAttribute(mm_scores_kernel, cudaFuncAttributeMaxDynamicSharedMemorySize, SM128);
    cudaFuncSetAttribute(mm_ctx_kernel,    cudaFuncAttributeMaxDynamicSharedMemorySize, SM64);

    // 0. weight prep (transpose + split)
    prep_w_kernel<<<dim3(DM/32, DM/32), 256>>>(W_in, wInh, wInl, DM, DM);
    prep_w_kernel<<<dim3(DM/32, DM/32), 256>>>(Wq,  wQh,  wQl,  DM, DM);
    prep_w_kernel<<<dim3(DM/32, DM/32), 256>>>(Wk,  wKh,  wKl,  DM, DM);
    prep_w_kernel<<<dim3(DM/32, DM/32), 256>>>(Wv,  wVh,  wVl,  DM, DM);
    prep_w_kernel<<<dim3(DM/32, DM/32), 256>>>(Wo,  wOh,  wOl,  DM, DM);
    prep_w_kernel<<<dim3(DM/32, DM/32), 256>>>(W2,  w2h,  w2l,  DM, DM);
    prep_w_kernel<<<dim3(DFF/32, DM/32), 256>>>(Wf1, wF1h, wF1l, DFF, DM);
    prep_w_kernel<<<dim3(DM/32, DFF/32), 256>>>(Wf2, wF2h, wF2l, DM, DFF);

    // 1. LN1 -> hi/lo only
    ln_kernel<0><<<S, 256>>>(x, g1, beta1, nullptr, n1h, n1l);

    // 2. h = norm1 @ W_in + b_in  (hi/lo only)
    mm_dense_kernel<0,0,0,1><<<dim3(DM/128, S/128), 256, SM128>>>(
        n1h, n1l, wInh, wInl, b_in, nullptr, nullptr, hh, hl, DM, DM);

    // 3. q/k/v
    mm_qkv_kernel<<<dim3(DM/128, S/128, 3), 256, SM128>>>(
        hh, hl, wQh, wQl, bq, qh, ql, wKh, wKl, bk, kh, kl, wVh, wVl, bv, vh, vl);

    // 3b. V transpose per head
    prep_vt_kernel<<<dim3(S/32, DK/32, NH), 256>>>(vh, vl, vth, vtl);

    // 4. scores -> attn fp32; 5. softmax -> attn fp32 + P hi/lo
    mm_scores_kernel<<<dim3(S/128, S/128, NH), 256, SM128>>>(qh, ql, kh, kl, attn);
    softmax_kernel<<<NH * S, 256>>>(attn, pph, ppl);

    // 6. ctx = P @ V (hi/lo only)
    mm_ctx_kernel<<<dim3(S/128, NH), 256, SM64>>>(pph, ppl, vth, vtl, ctxh, ctxl);

    // 7. mha = ctx @ Wo + bo (hi/lo only)
    mm_dense_kernel<0,0,0,1><<<dim3(DM/128, S/128), 256, SM128>>>(
        ctxh, ctxl, wOh, wOl, bo, nullptr, nullptr, mhah, mhal, DM, DM);

    // 8. part1 = x + mha @ W2 + b2 (fp32)
    mm_dense_kernel<1,0,1,0><<<dim3(DM/128, S/128), 256, SM128>>>(
        mhah, mhal, w2h, w2l, b2, x, p_part1, nullptr, nullptr, DM, DM);

    // 9. LN2 -> fp32 + hi/lo
    ln_kernel<1><<<S, 256>>>(p_part1, g2, beta2, p_norm2, n2h, n2l);

    // 10. ff1 = relu(norm2 @ Wf1 + bf1) (hi/lo only)
    mm_dense_kernel<0,1,0,1><<<dim3(DFF/128, S/128), 256, SM128>>>(
        n2h, n2l, wF1h, wF1l, bf1, nullptr, nullptr, f1h, f1l, DFF, DM);

    // 11. out = norm2 + ff1 @ Wf2 + bf2 (fp32)
    mm_dense_kernel<1,0,1,0><<<dim3(DM/128, S/128), 256, SM128>>>(
        f1h, f1l, wF2h, wF2l, bf2, p_norm2, out, nullptr, nullptr, DM, DFF);
}